// round 7
// baseline (speedup 1.0000x reference)
#include <cuda_runtime.h>
#include <cuda.h>
#include <cstdint>

// EmbedWeighted == out(B,D) = inputs(B,V) @ embeddings(V,D)
#define B_DIM 2048
#define V_DIM 2000
#define D_DIM 64
#define NSPLIT 8
#define KSPLIT 256           // splits 0..6: 256; split 7: 208 (TMA zero-fills OOB)
#define KC 32                // k per pipeline stage
#define NSTAGE 4
#define NTHREADS 256
#define MTILE 64
#define NMTILE (B_DIM / MTILE)          // 32
#define ASLOT 8192           // 64 rows x 128 B (SW128)
#define E_STRIDE 72          // floats; bank (8t+g)%32 distinct -> conflict-free
#define ESLOT (KC * E_STRIDE * 4)       // 9216 B
#define DYN_BYTES (1024 + NSTAGE * (ASLOT + ESLOT))   // ~70.7 KB -> 2 CTAs/SM

__device__ float g_partials[NSPLIT][B_DIM][D_DIM];   // 4 MB static scratch
__device__ unsigned g_arrive[NMTILE];                // zero-init, self-resetting
__device__ unsigned g_done[NMTILE];

static __device__ __forceinline__ uint32_t f2tf32(float f) {
    uint32_t r; asm("cvt.rna.tf32.f32 %0, %1;" : "=r"(r) : "f"(f)); return r;
}
static __device__ __forceinline__ uint32_t smem_u32(const void* p) {
    return (uint32_t)__cvta_generic_to_shared(p);
}
static __device__ __forceinline__ uint32_t lds32(uint32_t a) {
    uint32_t v; asm("ld.shared.b32 %0, [%1];" : "=r"(v) : "r"(a)); return v;
}
static __device__ __forceinline__ float lds32f(uint32_t a) {
    float v; asm("ld.shared.f32 %0, [%1];" : "=f"(v) : "r"(a)); return v;
}
static __device__ __forceinline__ void mbar_init(uint32_t mbar, uint32_t cnt) {
    asm volatile("mbarrier.init.shared.b64 [%0], %1;" :: "r"(mbar), "r"(cnt) : "memory");
}
static __device__ __forceinline__ void mbar_expect_tx(uint32_t mbar, uint32_t bytes) {
    asm volatile("mbarrier.arrive.expect_tx.shared.b64 _, [%0], %1;"
                 :: "r"(mbar), "r"(bytes) : "memory");
}
static __device__ __forceinline__ void mbar_wait(uint32_t mbar, uint32_t parity) {
    uint32_t done;
    asm volatile("{\n\t.reg .pred p;\n\t"
                 "mbarrier.try_wait.parity.acquire.cta.shared::cta.b64 p, [%1], %2;\n\t"
                 "selp.b32 %0,1,0,p;\n\t}"
                 : "=r"(done) : "r"(mbar), "r"(parity) : "memory");
    while (!done) {
        asm volatile("{\n\t.reg .pred p;\n\t"
                     "mbarrier.try_wait.parity.acquire.cta.shared::cta.b64 p, [%1], %2, 0x989680;\n\t"
                     "selp.b32 %0,1,0,p;\n\t}"
                     : "=r"(done) : "r"(mbar), "r"(parity) : "memory");
    }
}
static __device__ __forceinline__ void tma_load_2d(uint32_t smem_dst, const CUtensorMap* map,
                                                   int x, int y, uint32_t mbar) {
    asm volatile("cp.async.bulk.tensor.2d.shared::cta.global.tile.mbarrier::complete_tx::bytes "
                 "[%0], [%1, {%2, %3}], [%4];"
                 :: "r"(smem_dst), "l"(map), "r"(x), "r"(y), "r"(mbar) : "memory");
}
static __device__ __forceinline__ void cp_async16(uint32_t dst, const float* src, bool p) {
    int sz = p ? 16 : 0;   // src-size 0 => zero-fill
    asm volatile("cp.async.cg.shared.global [%0], [%1], 16, %2;"
                 :: "r"(dst), "l"(src), "r"(sz));
}
static __device__ __forceinline__ void cp_commit() {
    asm volatile("cp.async.commit_group;");
}
template <int N> static __device__ __forceinline__ void cp_wait() {
    asm volatile("cp.async.wait_group %0;" :: "n"(N));
}

// 256 threads, 8 warps, warp tile 32x16. CTA tile M=64, N=64.
// grid (8, 32) = 256 CTAs, 2 co-resident per SM.
__global__ __launch_bounds__(NTHREADS, 2)
void embedweighted_occ2(const __grid_constant__ CUtensorMap tmapA,
                        const float* __restrict__ emb,
                        float* __restrict__ out)
{
    extern __shared__ char dsm[];
    __shared__ __align__(8) unsigned long long s_full[NSTAGE];

    const uint32_t abase = (smem_u32(dsm) + 1023u) & ~1023u;   // SW128 alignment
    const uint32_t ebase = abase + NSTAGE * ASLOT;

    const int ksplit = blockIdx.x;
    const int mtile  = blockIdx.y;
    const int m_base = mtile * MTILE;
    const int k_base = ksplit * KSPLIT;
    const int k_len  = (ksplit < NSPLIT - 1) ? KSPLIT : (V_DIM - (NSPLIT - 1) * KSPLIT);
    const int nstages = (k_len + KC - 1) / KC;   // 8 or 7

    const int tid  = threadIdx.x;
    const int warp = tid >> 5;
    const int lane = tid & 31;
    const int g = lane >> 2;          // 0..7
    const int t = lane & 3;           // 0..3
    const int warp_m = warp & 1;      // 32-row slab (0..1)
    const int warp_n = warp >> 1;     // 16-col slab (0..3)

    float acc[2][2][4];
    #pragma unroll
    for (int i = 0; i < 2; i++)
        #pragma unroll
        for (int j = 0; j < 2; j++)
            #pragma unroll
            for (int r = 0; r < 4; r++) acc[i][j][r] = 0.0f;

    if (tid == 0) {
        #pragma unroll
        for (int s = 0; s < NSTAGE; s++) mbar_init(smem_u32(&s_full[s]), 1);
    }
    __syncthreads();   // mbarriers visible before TMA targets them

    // E stage loader: 512 16B chunks -> 2 per thread; zero-fill k >= V_DIM.
    auto loadE = [&](int s) {
        #pragma unroll
        for (int i = 0; i < 2; i++) {
            int idx = tid + i * NTHREADS;      // 0..511
            int r = idx >> 4;                  // 0..31 (k within stage)
            int q = idx & 15;                  // float4 within 64-wide row
            int k = k_base + s * KC + r;
            bool p = (k < V_DIM);
            cp_async16(ebase + (uint32_t)(s & 3) * ESLOT + (uint32_t)(r * E_STRIDE + q * 4) * 4u,
                       emb + (size_t)(p ? k : 0) * D_DIM + q * 4, p);
        }
        cp_commit();
    };

    // ---- prologue: stages 0..2 in flight for both A (TMA) and E (cp.async) ----
    if (tid == 0) {
        #pragma unroll
        for (int s = 0; s < 3; s++) {
            uint32_t mb = smem_u32(&s_full[s]);
            mbar_expect_tx(mb, ASLOT);
            tma_load_2d(abase + s * ASLOT, &tmapA, k_base + s * KC, m_base, mb);
        }
    }
    #pragma unroll
    for (int s = 0; s < 3; s++) loadE(s);

    // ---- mainloop ----
    const uint32_t xg = (uint32_t)g << 4;   // SW128 XOR term for A frags
    for (int it = 0; it < nstages; it++) {
        cp_wait<2>();      // E group for stage it done (2 newer pending)
        __syncthreads();   // E visible CTA-wide; all threads done with stage it-1
        mbar_wait(smem_u32(&s_full[it & 3]), (uint32_t)((it >> 2) & 1));

        // issue stage it+3 immediately (slot (it+3)&3 freed: stage it-1 consumers
        // finished before the barrier above)
        {
            int s = it + 3;
            if (s < nstages) {
                if (tid == 0) {
                    uint32_t mb = smem_u32(&s_full[s & 3]);
                    mbar_expect_tx(mb, ASLOT);
                    tma_load_2d(abase + (uint32_t)(s & 3) * ASLOT, &tmapA,
                                k_base + s * KC, m_base, mb);
                }
                loadE(s);
            } else {
                cp_commit();   // keep cp.async group accounting uniform
            }
        }

        const uint32_t Ab = abase + (uint32_t)(it & 3) * ASLOT;
        const uint32_t Eb = ebase + (uint32_t)(it & 3) * ESLOT;
        #pragma unroll
        for (int kk = 0; kk < KC; kk += 8) {
            uint32_t a[2][4], b[2][2];
            const uint32_t c0 = (uint32_t)((kk + t) * 4), c1 = c0 + 16;
            #pragma unroll
            for (int mt = 0; mt < 2; mt++) {
                uint32_t r0 = (uint32_t)(warp_m * 32 + mt * 16 + g) * 128;
                uint32_t r1 = r0 + 8 * 128;
                a[mt][0] = lds32(Ab + r0 + (c0 ^ xg));
                a[mt][1] = lds32(Ab + r1 + (c0 ^ xg));
                a[mt][2] = lds32(Ab + r0 + (c1 ^ xg));
                a[mt][3] = lds32(Ab + r1 + (c1 ^ xg));
            }
            #pragma unroll
            for (int nt = 0; nt < 2; nt++) {
                uint32_t col = (uint32_t)(warp_n * 16 + nt * 8 + g);
                b[nt][0] = f2tf32(lds32f(Eb + ((uint32_t)(kk + t)     * E_STRIDE + col) * 4u));
                b[nt][1] = f2tf32(lds32f(Eb + ((uint32_t)(kk + t + 4) * E_STRIDE + col) * 4u));
            }
            #pragma unroll
            for (int mt = 0; mt < 2; mt++)
                #pragma unroll
                for (int nt = 0; nt < 2; nt++)
                    asm volatile(
                        "mma.sync.aligned.m16n8k8.row.col.f32.tf32.tf32.f32 "
                        "{%0,%1,%2,%3}, {%4,%5,%6,%7}, {%8,%9}, {%0,%1,%2,%3};"
                        : "+f"(acc[mt][nt][0]), "+f"(acc[mt][nt][1]),
                          "+f"(acc[mt][nt][2]), "+f"(acc[mt][nt][3])
                        : "r"(a[mt][0]), "r"(a[mt][1]), "r"(a[mt][2]), "r"(a[mt][3]),
                          "r"(b[nt][0]), "r"(b[nt][1]));
        }
    }

    // ---- write 64x64 fp32 partial tile ----
    float* pp = &g_partials[ksplit][m_base][0];
    #pragma unroll
    for (int mt = 0; mt < 2; mt++) {
        int m0 = warp_m * 32 + mt * 16;
        #pragma unroll
        for (int nt = 0; nt < 2; nt++) {
            int n0 = warp_n * 16 + nt * 8 + 2 * t;
            pp[(m0 + g)     * D_DIM + n0]     = acc[mt][nt][0];
            pp[(m0 + g)     * D_DIM + n0 + 1] = acc[mt][nt][1];
            pp[(m0 + g + 8) * D_DIM + n0]     = acc[mt][nt][2];
            pp[(m0 + g + 8) * D_DIM + n0 + 1] = acc[mt][nt][3];
        }
    }

    // ---- fused deterministic split-K reduction ----
    // All 256 CTAs co-resident (occupancy 2, capacity 296) -> spin is safe.
    __syncthreads();
    if (tid == 0) {
        __threadfence();                       // release this CTA's partial stores
        atomicAdd(&g_arrive[mtile], 1u);
        unsigned v;
        do {
            asm volatile("ld.acquire.gpu.u32 %0, [%1];" : "=r"(v) : "l"(&g_arrive[mtile]));
            if (v >= NSPLIT) break;
            __nanosleep(64);
        } while (true);
    }
    __syncthreads();   // propagate tid0's acquire CTA-wide

    if (tid < 128) {   // this CTA reduces rows [m_base + ksplit*8, +8): 128 float4
        int r = tid >> 4, q = tid & 15;
        int off = (m_base + ksplit * 8 + r) * (D_DIM / 4) + q;
        const float4* p = reinterpret_cast<const float4*>(&g_partials[0][0][0]);
        float4 s = p[off];
        #pragma unroll
        for (int sp = 1; sp < NSPLIT; sp++) {   // fixed order -> deterministic
            float4 v = p[(size_t)sp * (B_DIM * D_DIM / 4) + off];
            s.x += v.x; s.y += v.y; s.z += v.z; s.w += v.w;
        }
        reinterpret_cast<float4*>(out)[off] = s;
    }

    __syncthreads();
    if (tid == 0) {   // reset counters for graph replay
        unsigned d = atomicAdd(&g_done[mtile], 1u);
        if (d == NSPLIT - 1) {
            atomicExch(&g_arrive[mtile], 0u);
            atomicExch(&g_done[mtile], 0u);
        }
    }
}

// ---- host ----
typedef CUresult (*EncodeTiledFn)(CUtensorMap*, CUtensorMapDataType, cuuint32_t, void*,
                                  const cuuint64_t*, const cuuint64_t*, const cuuint32_t*,
                                  const cuuint32_t*, CUtensorMapInterleave, CUtensorMapSwizzle,
                                  CUtensorMapL2promotion, CUtensorMapFloatOOBfill);

extern "C" void kernel_launch(void* const* d_in, const int* in_sizes, int n_in,
                              void* d_out, int out_size)
{
    void* inputs            = (void*)d_in[0];          // (B, V) fp32
    const float* embeddings = (const float*)d_in[1];   // (V, D) fp32
    float* out = (float*)d_out;                        // (B, D) fp32

    EncodeTiledFn encode = nullptr;
    {
        void* fn = nullptr;
#if CUDART_VERSION >= 12050
        cudaDriverEntryPointQueryResult qr;
        cudaGetDriverEntryPointByVersion("cuTensorMapEncodeTiled", &fn, 12000,
                                         cudaEnableDefault, &qr);
#else
        cudaDriverEntryPointQueryResult qr;
        cudaGetDriverEntryPoint("cuTensorMapEncodeTiled", &fn, cudaEnableDefault, &qr);
#endif
        encode = (EncodeTiledFn)fn;
    }

    CUtensorMap tmapA;
    {
        cuuint64_t dims[2]    = {(cuuint64_t)V_DIM, (cuuint64_t)B_DIM};
        cuuint64_t strides[1] = {(cuuint64_t)V_DIM * sizeof(float)};     // 8000 B
        cuuint32_t box[2]     = {KC, MTILE};                             // 128 B x 64 rows
        cuuint32_t estr[2]    = {1, 1};
        encode(&tmapA, CU_TENSOR_MAP_DATA_TYPE_FLOAT32, 2, inputs,
               dims, strides, box, estr,
               CU_TENSOR_MAP_INTERLEAVE_NONE, CU_TENSOR_MAP_SWIZZLE_128B,
               CU_TENSOR_MAP_L2_PROMOTION_L2_128B, CU_TENSOR_MAP_FLOAT_OOB_FILL_NONE);
    }

    cudaFuncSetAttribute(embedweighted_occ2,
                         cudaFuncAttributeMaxDynamicSharedMemorySize, DYN_BYTES);

    dim3 grid(NSPLIT, NMTILE);   // 256 CTAs, all co-resident at occupancy 2
    embedweighted_occ2<<<grid, NTHREADS, DYN_BYTES>>>(tmapA, embeddings, out);
}